// round 9
// baseline (speedup 1.0000x reference)
#include <cuda_runtime.h>
#include <cuda_fp16.h>
#include <cstdint>

#define TOKENS   64
#define NFEAT    8192
#define KFEAT    8192

#define KSPLIT    4
#define K_PER_CTA (KFEAT / KSPLIT)      // 2048 codes
#define CTA_N     128                   // 8 warps x 16 channels
#define ITER_C    32                    // codes per iteration
#define NITER     (K_PER_CTA / ITER_C)  // 64
#define PITCH     40                    // halves per smem A row (80B)

// stage layout (dynamic smem)
#define B_STAGE   16384                 // 128 rows x 128B
#define A_STAGE   (TOKENS * PITCH * 2)  // 5120B
#define STAGE_BYTES (B_STAGE + A_STAGE) // 21504
#define A_OFF     B_STAGE
#define NSTAGE    4
#define SMEM_TOTAL (NSTAGE * STAGE_BYTES)   // 86016

// scratch
__device__ __align__(16) __half g_x16[TOKENS * KFEAT];            // 1MB, K-permuted fp16 x
__device__ float g_sumx4[TOKENS * 4];
__device__ __align__(16) float g_part[KSPLIT][TOKENS * NFEAT];    // 8MB

// ---------------------------------------------------------------------------
// Prep: x16 with per-16-group permutation sigma(j)=((j>>3)&1)*2+(j&1)+((j>>1)&3)*4
// ---------------------------------------------------------------------------
__global__ __launch_bounds__(128) void prep_kernel(const float* __restrict__ x) {
    __shared__ float red[128];
    const int t = blockIdx.x, qtr = blockIdx.y, tid = threadIdx.x;
    const int g = qtr * 128 + tid;               // 16-code group index (0..511)
    const float* xr = x + (size_t)t * KFEAT;
    float v[16];
#pragma unroll
    for (int i = 0; i < 4; i++) {
        float4 f = reinterpret_cast<const float4*>(xr + g * 16)[i];
        v[i * 4 + 0] = f.x; v[i * 4 + 1] = f.y; v[i * 4 + 2] = f.z; v[i * 4 + 3] = f.w;
    }
    float sm = 0.f;
    unsigned short w[16];
#pragma unroll
    for (int j = 0; j < 16; j++) {
        int s = ((j >> 3) & 1) * 2 + (j & 1) + ((j >> 1) & 3) * 4;
        __half h = __float2half_rn(v[s]);
        sm += __half2float(h);
        w[j] = __half_as_ushort(h);
    }
    uint4* dst = reinterpret_cast<uint4*>(g_x16 + (size_t)t * KFEAT + g * 16);
    dst[0] = make_uint4((uint32_t)w[0] | ((uint32_t)w[1] << 16),
                        (uint32_t)w[2] | ((uint32_t)w[3] << 16),
                        (uint32_t)w[4] | ((uint32_t)w[5] << 16),
                        (uint32_t)w[6] | ((uint32_t)w[7] << 16));
    dst[1] = make_uint4((uint32_t)w[8] | ((uint32_t)w[9] << 16),
                        (uint32_t)w[10] | ((uint32_t)w[11] << 16),
                        (uint32_t)w[12] | ((uint32_t)w[13] << 16),
                        (uint32_t)w[14] | ((uint32_t)w[15] << 16));
    red[tid] = sm; __syncthreads();
    for (int s = 64; s > 0; s >>= 1) { if (tid < s) red[tid] += red[tid + s]; __syncthreads(); }
    if (tid == 0) g_sumx4[t * 4 + qtr] = red[0];
}

// ---------------------------------------------------------------------------
__device__ __forceinline__ void cpa16(uint32_t dst, const void* src) {
    asm volatile("cp.async.cg.shared.global [%0], [%1], 16;\n" :: "r"(dst), "l"(src));
}
#define CP_COMMIT() asm volatile("cp.async.commit_group;\n" ::: "memory")
#define CP_WAIT2()  asm volatile("cp.async.wait_group 2;\n" ::: "memory")

__device__ __forceinline__ uint32_t pack2(uint32_t a, uint32_t b) {
    uint32_t r;
    asm("prmt.b32 %0, %1, %2, 0x5410;" : "=r"(r) : "r"(a), "r"(b));
    return r;
}
__device__ __forceinline__ void mma16816(float* d, const uint32_t* a, uint32_t b0, uint32_t b1) {
    asm volatile(
        "mma.sync.aligned.m16n8k16.row.col.f32.f16.f16.f32 "
        "{%0,%1,%2,%3},{%4,%5,%6,%7},{%8,%9},{%0,%1,%2,%3};"
        : "+f"(d[0]), "+f"(d[1]), "+f"(d[2]), "+f"(d[3])
        : "r"(a[0]), "r"(a[1]), "r"(a[2]), "r"(a[3]), "r"(b0), "r"(b1));
}
#define LDS128(R, addr)                                                        \
    asm volatile("ld.shared.v4.u32 {%0,%1,%2,%3}, [%4];"                       \
        : "=r"((R).x), "=r"((R).y), "=r"((R).z), "=r"((R).w) : "r"(addr))

// ---------------------------------------------------------------------------
// GEMM: B streamed via cp.async 4-stage smem ring (96KB in flight/SM).
// ---------------------------------------------------------------------------
__global__ __launch_bounds__(256, 2) void gemm_kernel(const int* __restrict__ q) {
    extern __shared__ __align__(16) uint8_t smem[];
    const int tid  = threadIdx.x;
    const int warp = tid >> 5;
    const int lane = tid & 31;
    const uint32_t sbase = (uint32_t)__cvta_generic_to_shared(smem);

    const int blockN = blockIdx.x * CTA_N;
    const int kb = blockIdx.y * K_PER_CTA;

    // ---- producer mapping ----
    // B: thread -> row=tid>>1, h=tid&1; 4 x 16B at cols 4h..4h+3 (XOR swizzle)
    const int brow = tid >> 1;
    const int bh   = tid & 1;
    const int* bsrc = q + (size_t)(blockN + brow) * KFEAT + kb;
    const int bx7 = brow & 7;
    // A: thread -> arow=tid>>2, aseg=tid&3 (16B each)
    const int arow = tid >> 2;
    const int aseg = tid & 3;
    const __half* asrc = g_x16 + (size_t)arow * KFEAT + kb + aseg * 8;
    const uint32_t adst = (uint32_t)(arow * PITCH + aseg * 8) * 2;

#define LOAD_STAGE(c) do {                                                      \
    uint32_t st_ = sbase + (uint32_t)((c) & (NSTAGE - 1)) * STAGE_BYTES;        \
    const int* bs_ = bsrc + (c) * ITER_C;                                       \
    _Pragma("unroll")                                                           \
    for (int j = 0; j < 4; j++) {                                               \
        int col = bh * 4 + j;                                                   \
        cpa16(st_ + (uint32_t)(brow * 128 + ((col ^ bx7) * 16)), bs_ + col * 4);\
    }                                                                           \
    cpa16(st_ + A_OFF + adst, asrc + (size_t)(c) * ITER_C);                     \
    CP_COMMIT();                                                                \
} while (0)

    // prologue: stages 0,1,2
    LOAD_STAGE(0); LOAD_STAGE(1); LOAD_STAGE(2);

    // ---- consumer mapping ----
    const int n0 = warp * 16;                    // local channel base
    const int wr0 = n0 + (lane >> 2);            // B fragment rows (local)
    const int wr1 = wr0 + 8;
    const int cl  = lane & 3;
    const int rl = lane & 15;
    const int kh = (lane >> 4) * 8;

    float acc[4][2][4];
#pragma unroll
    for (int mi = 0; mi < 4; mi++)
#pragma unroll
        for (int nf = 0; nf < 2; nf++)
#pragma unroll
            for (int j = 0; j < 4; j++) acc[mi][nf][j] = 0.f;

    for (int i = 0; i < NITER; i++) {
        CP_WAIT2();
        __syncthreads();

        if (i + 3 < NITER) LOAD_STAGE(i + 3); else CP_COMMIT();

        const uint32_t stg = sbase + (uint32_t)(i & (NSTAGE - 1)) * STAGE_BYTES;

        // B fragments from smem (4 x LDS.128), dequant via PRMT
        uint32_t bf[2][2][2];   // [nf][s][reg]
#pragma unroll
        for (int s = 0; s < 2; s++) {
            int c0 = s * 4 + cl;
            int4 w0, w1;
            LDS128(w0, stg + (uint32_t)(wr0 * 128 + ((c0 ^ (wr0 & 7)) * 16)));
            LDS128(w1, stg + (uint32_t)(wr1 * 128 + ((c0 ^ (wr1 & 7)) * 16)));
            bf[0][s][0] = pack2((uint32_t)w0.x, (uint32_t)w0.y);
            bf[0][s][1] = pack2((uint32_t)w0.z, (uint32_t)w0.w);
            bf[1][s][0] = pack2((uint32_t)w1.x, (uint32_t)w1.y);
            bf[1][s][1] = pack2((uint32_t)w1.z, (uint32_t)w1.w);
        }

        // A fragments + MMA: 2 k16 steps x 4 m-tiles x 2 n-frags
        const uint32_t abase = stg + A_OFF;
#pragma unroll
        for (int s = 0; s < 2; s++) {
            uint32_t a[4][4];
#pragma unroll
            for (int mi = 0; mi < 4; mi++) {
                uint32_t addr = abase + (uint32_t)((mi * 16 + rl) * PITCH + s * 16 + kh) * 2;
                asm volatile(
                    "ldmatrix.sync.aligned.m8n8.x4.shared.b16 {%0,%1,%2,%3}, [%4];"
                    : "=r"(a[mi][0]), "=r"(a[mi][1]), "=r"(a[mi][2]), "=r"(a[mi][3])
                    : "r"(addr));
            }
#pragma unroll
            for (int mi = 0; mi < 4; mi++)
#pragma unroll
                for (int nf = 0; nf < 2; nf++)
                    mma16816(acc[mi][nf], a[mi], bf[nf][s][0], bf[nf][s][1]);
        }
    }

    // epilogue: raw partial dots
    float* pp = &g_part[blockIdx.y][0];
    const int kc2 = (lane & 3) * 2;
#pragma unroll
    for (int mi = 0; mi < 4; mi++)
#pragma unroll
        for (int nf = 0; nf < 2; nf++) {
            int col = blockN + warp * 16 + nf * 8 + kc2;
            int t0  = mi * 16 + (lane >> 2);
            *reinterpret_cast<float2*>(&pp[(size_t)t0 * NFEAT + col]) =
                make_float2(acc[mi][nf][0], acc[mi][nf][1]);
            *reinterpret_cast<float2*>(&pp[(size_t)(t0 + 8) * NFEAT + col]) =
                make_float2(acc[mi][nf][2], acc[mi][nf][3]);
        }
#undef LOAD_STAGE
}

// ---------------------------------------------------------------------------
// Reduce: y = s * (2^24 * sum_splits - zp * sumx_t) + bias
// ---------------------------------------------------------------------------
__global__ void reduce_kernel(const float* __restrict__ scales,
                              const int* __restrict__ zp,
                              const float* __restrict__ bias,
                              float* __restrict__ out) {
    int i = blockIdx.x * blockDim.x + threadIdx.x;     // float4 units
    int col4 = i & (NFEAT / 4 - 1);
    int t    = i >> 11;
    float4 a = reinterpret_cast<const float4*>(g_part[0])[i];
    float4 b = reinterpret_cast<const float4*>(g_part[1])[i];
    float4 c = reinterpret_cast<const float4*>(g_part[2])[i];
    float4 d = reinterpret_cast<const float4*>(g_part[3])[i];
    float4 sc = reinterpret_cast<const float4*>(scales)[col4];
    float4 bi = reinterpret_cast<const float4*>(bias)[col4];
    int4   zi = reinterpret_cast<const int4*>(zp)[col4];
    float sx = (g_sumx4[t * 4 + 0] + g_sumx4[t * 4 + 1]) +
               (g_sumx4[t * 4 + 2] + g_sumx4[t * 4 + 3]);
    const float SC = 16777216.0f;  // 2^24
    float4 r;
    r.x = bi.x + sc.x * (SC * ((a.x + b.x) + (c.x + d.x)) - (float)zi.x * sx);
    r.y = bi.y + sc.y * (SC * ((a.y + b.y) + (c.y + d.y)) - (float)zi.y * sx);
    r.z = bi.z + sc.z * (SC * ((a.z + b.z) + (c.z + d.z)) - (float)zi.z * sx);
    r.w = bi.w + sc.w * (SC * ((a.w + b.w) + (c.w + d.w)) - (float)zi.w * sx);
    reinterpret_cast<float4*>(out)[i] = r;
}

// ---------------------------------------------------------------------------
extern "C" void kernel_launch(void* const* d_in, const int* in_sizes, int n_in,
                              void* d_out, int out_size) {
    const float* x    = (const float*)d_in[0];
    const int*   qw   = (const int*)d_in[1];
    const float* sc   = (const float*)d_in[2];
    const int*   zp   = (const int*)d_in[3];
    const float* bias = (const float*)d_in[4];
    float*       out  = (float*)d_out;
    (void)in_sizes; (void)n_in; (void)out_size;

    cudaFuncSetAttribute(gemm_kernel, cudaFuncAttributeMaxDynamicSharedMemorySize, SMEM_TOTAL);

    prep_kernel<<<dim3(TOKENS, 4), 128>>>(x);
    gemm_kernel<<<dim3(NFEAT / CTA_N, KSPLIT), 256, SMEM_TOTAL>>>(qw);
    reduce_kernel<<<(TOKENS * NFEAT / 4) / 256, 256>>>(sc, zp, bias, out);
}

// round 10
// speedup vs baseline: 2.0899x; 2.0899x over previous
#include <cuda_runtime.h>
#include <cuda_fp16.h>
#include <cstdint>

#define TOKENS   64
#define NFEAT    8192
#define KFEAT    8192

#define KSPLIT    4
#define K_PER_CTA (KFEAT / KSPLIT)      // 2048 codes
#define CTA_N     128                   // 8 warps x 16 channels
#define ITER_C    64                    // codes per iteration
#define NITER     (K_PER_CTA / ITER_C)  // 32
#define PITCH     72                    // halves per smem A row (144B, conflict-free)
#define ASTAGES   4

// scratch
__device__ __align__(16) __half g_x16[TOKENS * KFEAT];            // 1MB, K-permuted fp16 x
__device__ float g_sumx[TOKENS];
__device__ __align__(16) float g_part[KSPLIT][TOKENS * NFEAT];    // 8MB

// ---------------------------------------------------------------------------
// Prep: x16 with per-16-group permutation sigma(j)=((j>>3)&1)*2+(j&1)+((j>>1)&3)*4
// 64 blocks x 512 threads; one 16-code group per thread, shfl reduction.
// ---------------------------------------------------------------------------
__global__ __launch_bounds__(512) void prep_kernel(const float* __restrict__ x) {
    __shared__ float s_w[16];
    const int t = blockIdx.x, tid = threadIdx.x;
    const int g = tid;                           // 16-code group index (0..511)
    const float* xr = x + (size_t)t * KFEAT;
    float4 f[4];
#pragma unroll
    for (int i = 0; i < 4; i++)
        f[i] = reinterpret_cast<const float4*>(xr + g * 16)[i];
    float v[16];
#pragma unroll
    for (int i = 0; i < 4; i++) {
        v[i * 4 + 0] = f[i].x; v[i * 4 + 1] = f[i].y;
        v[i * 4 + 2] = f[i].z; v[i * 4 + 3] = f[i].w;
    }
    float sm = 0.f;
    unsigned short w[16];
#pragma unroll
    for (int j = 0; j < 16; j++) {
        int s = ((j >> 3) & 1) * 2 + (j & 1) + ((j >> 1) & 3) * 4;
        __half h = __float2half_rn(v[s]);
        sm += __half2float(h);
        w[j] = __half_as_ushort(h);
    }
    uint4* dst = reinterpret_cast<uint4*>(g_x16 + (size_t)t * KFEAT + g * 16);
    dst[0] = make_uint4((uint32_t)w[0] | ((uint32_t)w[1] << 16),
                        (uint32_t)w[2] | ((uint32_t)w[3] << 16),
                        (uint32_t)w[4] | ((uint32_t)w[5] << 16),
                        (uint32_t)w[6] | ((uint32_t)w[7] << 16));
    dst[1] = make_uint4((uint32_t)w[8] | ((uint32_t)w[9] << 16),
                        (uint32_t)w[10] | ((uint32_t)w[11] << 16),
                        (uint32_t)w[12] | ((uint32_t)w[13] << 16),
                        (uint32_t)w[14] | ((uint32_t)w[15] << 16));
    // warp reduce + cross-warp
#pragma unroll
    for (int o = 16; o > 0; o >>= 1) sm += __shfl_xor_sync(0xFFFFFFFFu, sm, o);
    if ((tid & 31) == 0) s_w[tid >> 5] = sm;
    __syncthreads();
    if (tid < 32) {
        float r = (tid < 16) ? s_w[tid] : 0.f;
#pragma unroll
        for (int o = 8; o > 0; o >>= 1) r += __shfl_xor_sync(0xFFFFFFFFu, r, o);
        if (tid == 0) g_sumx[t] = r;
    }
}

// ---------------------------------------------------------------------------
__device__ __forceinline__ void cpa16(uint32_t dst, const void* src) {
    asm volatile("cp.async.ca.shared.global [%0], [%1], 16;\n" :: "r"(dst), "l"(src));
}
#define CP_COMMIT() asm volatile("cp.async.commit_group;\n" ::: "memory")
#define CP_WAIT2()  asm volatile("cp.async.wait_group 2;\n" ::: "memory")

__device__ __forceinline__ int4 ldg_cs(const int* p) {
    int4 v;
    asm volatile("ld.global.cs.v4.b32 {%0,%1,%2,%3}, [%4];"
        : "=r"(v.x), "=r"(v.y), "=r"(v.z), "=r"(v.w) : "l"(p));
    return v;
}
// [a.b0, 0, b.b0, 0] -> half2 {ca*2^-24, cb*2^-24} (exact), one PRMT.
__device__ __forceinline__ uint32_t pack2(uint32_t a, uint32_t b) {
    uint32_t r;
    asm("prmt.b32 %0, %1, %2, 0x5410;" : "=r"(r) : "r"(a), "r"(b));
    return r;
}
__device__ __forceinline__ void mma16816(float* d, const uint32_t* a, uint32_t b0, uint32_t b1) {
    asm volatile(
        "mma.sync.aligned.m16n8k16.row.col.f32.f16.f16.f32 "
        "{%0,%1,%2,%3},{%4,%5,%6,%7},{%8,%9},{%0,%1,%2,%3};"
        : "+f"(d[0]), "+f"(d[1]), "+f"(d[2]), "+f"(d[3])
        : "r"(a[0]), "r"(a[1]), "r"(a[2]), "r"(a[3]), "r"(b0), "r"(b1));
}

// ---------------------------------------------------------------------------
// GEMM: 64tok x 128ch x 2048codes per CTA; 256 CTAs, 2/SM.
// Per-segment software pipeline: each k16 segment converts, reloads (next
// iter), ldmatrix, mma -> every B load gets ~1 full iteration of slack.
// ---------------------------------------------------------------------------
__global__ __launch_bounds__(256, 2) void gemm_kernel(const int* __restrict__ q) {
    __shared__ __align__(16) __half sA[ASTAGES][TOKENS * PITCH];   // 4 x 9216 B

    const int tid  = threadIdx.x;
    const int warp = tid >> 5;
    const int lane = tid & 31;

    const int n0 = blockIdx.x * CTA_N + warp * 16;
    const int kb = blockIdx.y * K_PER_CTA;

    const int r0 = n0 + (lane >> 2);
    const int r1 = r0 + 8;
    const int qd4 = (lane & 3) * 4;

    const int* pB0 = q + (size_t)r0 * KFEAT + kb + qd4;
    const int* pB1 = q + (size_t)r1 * KFEAT + kb + qd4;

    // A staging: 64 rows x 64 halves (128B) per iter; 256 thr x 32B (2 segs)
    const int arow = tid >> 2;
    const int aseg = tid & 3;
    const __half* asrc = g_x16 + (size_t)arow * KFEAT + kb + aseg * 8;
    const uint32_t sbase = (uint32_t)__cvta_generic_to_shared(&sA[0][0]);
    const uint32_t ABUF  = TOKENS * PITCH * 2;
    const uint32_t adst  = (uint32_t)(arow * PITCH + aseg * 8) * 2;

    // B registers: one iteration (64 codes) = [nf][s], s=0..3
    int4 raw[2][4];
#pragma unroll
    for (int s = 0; s < 4; s++) {
        raw[0][s] = ldg_cs(pB0 + s * 16);
        raw[1][s] = ldg_cs(pB1 + s * 16);
    }
    // A cp.async prologue: iters 0,1,2
#pragma unroll
    for (int i = 0; i < 3; i++) {
        cpa16(sbase + i * ABUF + adst, asrc + (size_t)i * ITER_C);
        cpa16(sbase + i * ABUF + adst + 64, asrc + (size_t)i * ITER_C + 32);
        CP_COMMIT();
    }

    float acc[4][2][4];
#pragma unroll
    for (int mi = 0; mi < 4; mi++)
#pragma unroll
        for (int nf = 0; nf < 2; nf++)
#pragma unroll
            for (int j = 0; j < 4; j++) acc[mi][nf][j] = 0.f;

    const int rl = lane & 15;
    const int kh = (lane >> 4) * 8;

    for (int i = 0; i < NITER; i++) {
        CP_WAIT2();
        __syncthreads();

        // A for iter i+3
        if (i + 3 < NITER) {
            const __half* s3 = asrc + (size_t)(i + 3) * ITER_C;
            cpa16(sbase + ((i + 3) & 3) * ABUF + adst, s3);
            cpa16(sbase + ((i + 3) & 3) * ABUF + adst + 64, s3 + 32);
        }
        CP_COMMIT();

        const uint32_t abase = sbase + (uint32_t)(i & 3) * ABUF;
        const int off = (i + 1) * ITER_C;
        const bool more = (i + 1 < NITER);

#pragma unroll
        for (int s = 0; s < 4; s++) {
            // 1) dequant this segment (exact subnormal pack)
            uint32_t bf00 = pack2((uint32_t)raw[0][s].x, (uint32_t)raw[0][s].y);
            uint32_t bf01 = pack2((uint32_t)raw[0][s].z, (uint32_t)raw[0][s].w);
            uint32_t bf10 = pack2((uint32_t)raw[1][s].x, (uint32_t)raw[1][s].y);
            uint32_t bf11 = pack2((uint32_t)raw[1][s].z, (uint32_t)raw[1][s].w);

            // 2) immediately refill this segment for the NEXT iteration
            if (more) {
                raw[0][s] = ldg_cs(pB0 + off + s * 16);
                raw[1][s] = ldg_cs(pB1 + off + s * 16);
            }

            // 3) A fragments + 8 MMAs
            uint32_t a[4][4];
#pragma unroll
            for (int mi = 0; mi < 4; mi++) {
                uint32_t addr = abase + (uint32_t)((mi * 16 + rl) * PITCH + s * 16 + kh) * 2;
                asm volatile(
                    "ldmatrix.sync.aligned.m8n8.x4.shared.b16 {%0,%1,%2,%3}, [%4];"
                    : "=r"(a[mi][0]), "=r"(a[mi][1]), "=r"(a[mi][2]), "=r"(a[mi][3])
                    : "r"(addr));
            }
#pragma unroll
            for (int mi = 0; mi < 4; mi++) {
                mma16816(acc[mi][0], a[mi], bf00, bf01);
                mma16816(acc[mi][1], a[mi], bf10, bf11);
            }
        }
    }

    // epilogue: raw partial dots
    float* pp = &g_part[blockIdx.y][0];
    const int kc2 = (lane & 3) * 2;
#pragma unroll
    for (int mi = 0; mi < 4; mi++)
#pragma unroll
        for (int nf = 0; nf < 2; nf++) {
            int col = n0 + nf * 8 + kc2;
            int t0  = mi * 16 + (lane >> 2);
            *reinterpret_cast<float2*>(&pp[(size_t)t0 * NFEAT + col]) =
                make_float2(acc[mi][nf][0], acc[mi][nf][1]);
            *reinterpret_cast<float2*>(&pp[(size_t)(t0 + 8) * NFEAT + col]) =
                make_float2(acc[mi][nf][2], acc[mi][nf][3]);
        }
}

// ---------------------------------------------------------------------------
// Reduce: y = s * (2^24 * sum_splits - zp * sumx_t) + bias
// ---------------------------------------------------------------------------
__global__ void reduce_kernel(const float* __restrict__ scales,
                              const int* __restrict__ zp,
                              const float* __restrict__ bias,
                              float* __restrict__ out) {
    int i = blockIdx.x * blockDim.x + threadIdx.x;     // float4 units
    int col4 = i & (NFEAT / 4 - 1);
    int t    = i >> 11;
    float4 a = reinterpret_cast<const float4*>(g_part[0])[i];
    float4 b = reinterpret_cast<const float4*>(g_part[1])[i];
    float4 c = reinterpret_cast<const float4*>(g_part[2])[i];
    float4 d = reinterpret_cast<const float4*>(g_part[3])[i];
    float4 sc = reinterpret_cast<const float4*>(scales)[col4];
    float4 bi = reinterpret_cast<const float4*>(bias)[col4];
    int4   zi = reinterpret_cast<const int4*>(zp)[col4];
    float sx = g_sumx[t];
    const float SC = 16777216.0f;  // 2^24
    float4 r;
    r.x = bi.x + sc.x * (SC * ((a.x + b.x) + (c.x + d.x)) - (float)zi.x * sx);
    r.y = bi.y + sc.y * (SC * ((a.y + b.y) + (c.y + d.y)) - (float)zi.y * sx);
    r.z = bi.z + sc.z * (SC * ((a.z + b.z) + (c.z + d.z)) - (float)zi.z * sx);
    r.w = bi.w + sc.w * (SC * ((a.w + b.w) + (c.w + d.w)) - (float)zi.w * sx);
    reinterpret_cast<float4*>(out)[i] = r;
}

// ---------------------------------------------------------------------------
extern "C" void kernel_launch(void* const* d_in, const int* in_sizes, int n_in,
                              void* d_out, int out_size) {
    const float* x    = (const float*)d_in[0];
    const int*   qw   = (const int*)d_in[1];
    const float* sc   = (const float*)d_in[2];
    const int*   zp   = (const int*)d_in[3];
    const float* bias = (const float*)d_in[4];
    float*       out  = (float*)d_out;
    (void)in_sizes; (void)n_in; (void)out_size;

    prep_kernel<<<TOKENS, 512>>>(x);
    gemm_kernel<<<dim3(NFEAT / CTA_N, KSPLIT), 256>>>(qw);
    reduce_kernel<<<(TOKENS * NFEAT / 4) / 256, 256>>>(sc, zp, bias, out);
}